// round 14
// baseline (speedup 1.0000x reference)
#include <cuda_runtime.h>
#include <cuda_fp16.h>
#include <math.h>
#include <stddef.h>
#include <stdint.h>
#include <mma.h>

using namespace nvcuda;

// Problem dims (fixed)
#define B_   64
#define T_   512
#define D_   1024
#define H_   1024
#define L_   4
#define G_   4096           // 4*H
#define O_   256
#define TB_  (T_ * B_)      // 32768

#define NBLK 128            // persistent-kernel grid
#define NTHR 256

// ---------------------------------------------------------------------------
// Device scratch (static globals — no allocation allowed)
// ---------------------------------------------------------------------------
__device__ float  g_gates[(size_t)TB_ * G_];     // 512 MB
__device__ __half g_xh  [(size_t)TB_ * D_];      // 64 MB
__device__ __half g_wh  [(size_t)L_ * G_ * H_];  // 32 MB: ALL layers' Wih fp16
__device__ __half g_seqh0[(size_t)TB_ * H_];     // 64 MB
__device__ __half g_seqh1[(size_t)TB_ * H_];     // 64 MB
__device__ __half g_hA[B_ * H_];
__device__ __half g_hB[B_ * H_];

__device__ unsigned g_bar_count = 0;
__device__ unsigned g_bar_gen   = 0;
__device__ int      g_flags[NBLK * 32];          // one 128B line per block

// ---------------------------------------------------------------------------
// Atomic grid barrier (self-resetting; used ONCE per layer for init)
// ---------------------------------------------------------------------------
__device__ __forceinline__ void grid_barrier_atomic() {
    __threadfence();
    __syncthreads();
    if (threadIdx.x == 0) {
        unsigned gen = *(volatile unsigned*)&g_bar_gen;
        unsigned old = atomicAdd(&g_bar_count, 1u);
        if (old == NBLK - 1) {
            g_bar_count = 0;
            __threadfence();
            atomicAdd(&g_bar_gen, 1u);
        } else {
            while (*(volatile unsigned*)&g_bar_gen == gen) { }
        }
        __threadfence();
    }
    __syncthreads();
}

// ---------------------------------------------------------------------------
// Distributed flag barrier (per-step)
// ---------------------------------------------------------------------------
__device__ __forceinline__ void flag_barrier(int jb, int tid, int val) {
    __threadfence();
    __syncthreads();
    if (tid == 0)
        *((volatile int*)&g_flags[jb * 32]) = val;
    if (tid < NBLK) {
        volatile int* f = &g_flags[tid * 32];
        while (*f < val) { }
    }
    __syncthreads();
}

// ---------------------------------------------------------------------------
// cp.async helpers
// ---------------------------------------------------------------------------
__device__ __forceinline__ uint32_t smem_u32(const void* p) {
    uint32_t a;
    asm("{ .reg .u64 t; cvta.to.shared.u64 t, %1; cvt.u32.u64 %0, t; }"
        : "=r"(a) : "l"(p));
    return a;
}
__device__ __forceinline__ void cp16(uint32_t dst, const void* src) {
    asm volatile("cp.async.cg.shared.global [%0], [%1], 16;"
                 :: "r"(dst), "l"(src));
}
__device__ __forceinline__ void cp_commit() {
    asm volatile("cp.async.commit_group;" ::: "memory");
}
template <int N>
__device__ __forceinline__ void cp_wait() {
    asm volatile("cp.async.wait_group %0;" :: "n"(N) : "memory");
}

// fp16 mma: D(16x8,f32) += A(16x16,f16,row) * B(16x8,f16,col)
__device__ __forceinline__ void mma16(float* c,
                                      unsigned a0, unsigned a1,
                                      unsigned a2, unsigned a3,
                                      unsigned b0, unsigned b1) {
    asm volatile(
        "mma.sync.aligned.m16n8k16.row.col.f32.f16.f16.f32 "
        "{%0,%1,%2,%3}, {%4,%5,%6,%7}, {%8,%9}, {%0,%1,%2,%3};"
        : "+f"(c[0]), "+f"(c[1]), "+f"(c[2]), "+f"(c[3])
        : "r"(a0), "r"(a1), "r"(a2), "r"(a3), "r"(b0), "r"(b1));
}

__device__ __forceinline__ unsigned pack_h2(float x, float y) {
    __half2 h = __floats2half2_rn(x, y);
    return *reinterpret_cast<unsigned*>(&h);
}

// fast sigmoid / tanh (MUFU-based)
__device__ __forceinline__ float fsig(float x) {
    return __fdividef(1.0f, 1.0f + __expf(-x));
}
__device__ __forceinline__ float ftanh(float x) {
    return 1.0f - __fdividef(2.0f, __expf(2.0f * x) + 1.0f);
}

// ---------------------------------------------------------------------------
// One-time converts
// ---------------------------------------------------------------------------
__global__ void __launch_bounds__(256)
conv_x(const float* __restrict__ x)
{
    const int m = blockIdx.x;              // t*B + b
    const int t = m >> 6, b = m & 63;
    const float4* src = reinterpret_cast<const float4*>(
        x + ((size_t)b * T_ + t) * D_);
    __half2* dst = reinterpret_cast<__half2*>(g_xh + (size_t)m * D_);
    for (int i = threadIdx.x; i < D_ / 4; i += 256) {
        float4 v = src[i];
        dst[2 * i]     = __floats2half2_rn(v.x, v.y);
        dst[2 * i + 1] = __floats2half2_rn(v.z, v.w);
    }
}

// ALL layers' Wih fp32 -> g_wh fp16 (one launch)
__global__ void __launch_bounds__(256)
conv_w(const float* __restrict__ Wih_all)
{
    const int r = blockIdx.x;              // 0..(L*G-1)
    const float4* src = reinterpret_cast<const float4*>(
        Wih_all + (size_t)r * H_);
    __half2* dst = reinterpret_cast<__half2*>(g_wh + (size_t)r * H_);
    for (int i = threadIdx.x; i < H_ / 4; i += 256) {
        float4 v = src[i];
        dst[2 * i]     = __floats2half2_rn(v.x, v.y);
        dst[2 * i + 1] = __floats2half2_rn(v.z, v.w);
    }
}

// ===========================================================================
// fp16 input GEMM (proven):
//   gates[m, n] = bias[n] + sum_k A[m,k] * W[n,k]
// ===========================================================================
#define BM 128
#define BN 128
#define BKH 32
#define APH 40
#define STGH (BM * APH)
#define CPITCH 68
#define GEMM_SM_BYTES (4 * STGH * 2 + 512)

__device__ __forceinline__ void load_stage_h(__half* smh, int s, int c,
                                             const __half* __restrict__ A,
                                             const __half* __restrict__ W,
                                             int m0, int n0, int tid)
{
    const int k0 = c * BKH;
    __half* as = smh + s * STGH;
    __half* ws = smh + 2 * STGH + s * STGH;
#pragma unroll
    for (int i = 0; i < 2; i++) {
        int idx = tid + i * 256;
        int row = idx >> 2, seg = idx & 3;
        cp16(smem_u32(&as[row * APH + seg * 8]),
             A + (size_t)(m0 + row) * H_ + k0 + seg * 8);
    }
#pragma unroll
    for (int i = 0; i < 2; i++) {
        int idx = tid + i * 256;
        int row = idx >> 2, seg = idx & 3;
        cp16(smem_u32(&ws[row * APH + seg * 8]),
             W + (size_t)(n0 + row) * H_ + k0 + seg * 8);
    }
    cp_commit();
}

__global__ void __launch_bounds__(256)
gemm_gates_h(const __half* __restrict__ A,
             const float* __restrict__ bih_all,
             const float* __restrict__ bhh_all,
             int layer)
{
    __shared__ __align__(16) char smraw[GEMM_SM_BYTES];
    __half* smh   = reinterpret_cast<__half*>(smraw);
    float*  biasS = reinterpret_cast<float*>(smraw + 4 * STGH * 2);
    float*  Cbuf  = reinterpret_cast<float*>(smraw);

    const __half* W = g_wh + (size_t)layer * G_ * H_;

    const int tid = threadIdx.x;
    const int n0  = blockIdx.x * BN;
    const int m0  = blockIdx.y * BM;
    const int wid = tid >> 5;
    const int wm  = wid & 3;
    const int wn  = wid >> 2;

    if (tid < 128)
        biasS[tid] = bih_all[(size_t)layer * G_ + n0 + tid]
                   + bhh_all[(size_t)layer * G_ + n0 + tid];

    wmma::fragment<wmma::accumulator, 16, 16, 16, float> cf[2][4];
#pragma unroll
    for (int i = 0; i < 2; i++)
#pragma unroll
        for (int j = 0; j < 4; j++) wmma::fill_fragment(cf[i][j], 0.0f);

    load_stage_h(smh, 0, 0, A, W, m0, n0, tid);

    const int NC = H_ / BKH;
    for (int c = 0; c < NC; c++) {
        const int s = c & 1;
        if (c + 1 < NC) {
            load_stage_h(smh, s ^ 1, c + 1, A, W, m0, n0, tid);
            cp_wait<1>();
        } else {
            cp_wait<0>();
        }
        __syncthreads();

        const __half* as = smh + s * STGH;
        const __half* ws = smh + 2 * STGH + s * STGH;
#pragma unroll
        for (int kk = 0; kk < BKH; kk += 16) {
            wmma::fragment<wmma::matrix_a, 16, 16, 16, __half,
                           wmma::row_major> af[2];
            wmma::fragment<wmma::matrix_b, 16, 16, 16, __half,
                           wmma::col_major> bf[4];
#pragma unroll
            for (int i = 0; i < 2; i++)
                wmma::load_matrix_sync(af[i],
                    as + (wm * 32 + i * 16) * APH + kk, APH);
#pragma unroll
            for (int j = 0; j < 4; j++)
                wmma::load_matrix_sync(bf[j],
                    ws + (wn * 64 + j * 16) * APH + kk, APH);
#pragma unroll
            for (int i = 0; i < 2; i++)
#pragma unroll
                for (int j = 0; j < 4; j++)
                    wmma::mma_sync(cf[i][j], af[i], bf[j], cf[i][j]);
        }
        __syncthreads();
    }

#pragma unroll
    for (int half = 0; half < 2; half++) {
        if (wn == half) {
#pragma unroll
            for (int i = 0; i < 2; i++)
#pragma unroll
                for (int j = 0; j < 4; j++)
                    wmma::store_matrix_sync(
                        &Cbuf[(wm * 32 + i * 16) * CPITCH + j * 16],
                        cf[i][j], CPITCH, wmma::mem_row_major);
        }
        __syncthreads();
#pragma unroll
        for (int q = 0; q < 8; q++) {
            int lin = q * 256 + tid;
            int row = lin >> 4;
            int c4  = lin & 15;
            float4 v = *reinterpret_cast<const float4*>(&Cbuf[row * CPITCH + c4 * 4]);
            int n = half * 64 + c4 * 4;
            v.x += biasS[n + 0];
            v.y += biasS[n + 1];
            v.z += biasS[n + 2];
            v.w += biasS[n + 3];
            *reinterpret_cast<float4*>(
                &g_gates[(size_t)(m0 + row) * G_ + n0 + n]) = v;
        }
        __syncthreads();
    }
}

// ===========================================================================
// Persistent recurrent kernel v7: NPART 8 -> 4.
// 8 warps = 4 K-quarters (256 k) x 2 n-halves (2 gates each).
//   bw 64 regs, acc 32 regs -> room for a 4-deep load pipeline (a 64 regs).
//   LDS partial reduction halves; A loads duplicate x2 (cheap vs LDS).
// Gates for step t+1 prefetched BEFORE the flag barrier.
// ===========================================================================
#define PP 36
#define PRE_FL (64 * PP)
#define NPART 4
#define PSMEM_BYTES (NPART * PRE_FL * 4)       // 36,864 B

__device__ __forceinline__ void load_burst(unsigned a[4][4],
                                           const __half* __restrict__ hin,
                                           int kb, int grp, int tq)
{
#pragma unroll
    for (int mf = 0; mf < 4; mf++) {
        const unsigned* p0 = reinterpret_cast<const unsigned*>(
            hin + (mf * 16 + grp) * H_ + kb) + tq;
        const unsigned* p1 = p0 + 4 * H_;      // +8 rows
        a[mf][0] = __ldcg(p0);
        a[mf][1] = __ldcg(p1);
        a[mf][2] = __ldcg(p0 + 4);
        a[mf][3] = __ldcg(p1 + 4);
    }
}

__global__ void __launch_bounds__(NTHR, 1)
lstm_persist_tc(const float* __restrict__ Whh_all, int layer, int out_sel)
{
    extern __shared__ float preS[];            // [4][64][PP]

    const float* W      = Whh_all + (size_t)layer * G_ * H_;
    __half*      seqout = (out_sel == 0) ? g_seqh0 : g_seqh1;

    const int jb   = blockIdx.x;
    const int tid  = threadIdx.x;
    const int lane = tid & 31;
    const int wid  = tid >> 5;
    const int kq   = wid & 3;        // K-quarter: k in [kq*256, kq*256+256)
    const int nh   = wid >> 2;       // n-half: gates {0,1} or {2,3}
    const int grp  = lane >> 2;      // 0..7
    const int tq   = lane & 3;       // 0..3

    const int eb  = tid >> 2;
    const int ejj = (tid & 3) * 2;
    const int jg0 = jb * 8 + ejj;

    // Whh B-fragments -> registers (fp16): 16 k16 x 2 gates x 2 = 64 regs
    unsigned bw[16][2][2];
    {
#pragma unroll
        for (int nt = 0; nt < 2; nt++) {
            const int gr = (nh * 2 + nt) * H_ + jb * 8 + grp;
            const float* wr = W + (size_t)gr * H_ + kq * 256 + 2 * tq;
#pragma unroll
            for (int k16 = 0; k16 < 16; k16++) {
                bw[k16][nt][0] = pack_h2(wr[k16 * 16],     wr[k16 * 16 + 1]);
                bw[k16][nt][1] = pack_h2(wr[k16 * 16 + 8], wr[k16 * 16 + 9]);
            }
        }
    }

    // zero initial h + reset my flag
    reinterpret_cast<unsigned*>(g_hA)[jb * 256 + tid] = 0u;
    reinterpret_cast<unsigned*>(g_hB)[jb * 256 + tid] = 0u;
    if (tid == 0) g_flags[jb * 32] = 0;

    float2 creg = make_float2(0.0f, 0.0f);

    grid_barrier_atomic();

    // gates prefetch for t = 0
    const float* grow0 = g_gates + ((size_t)eb) * G_ + jg0;
    float2 G0 = *reinterpret_cast<const float2*>(grow0);
    float2 G1 = *reinterpret_cast<const float2*>(grow0 + H_);
    float2 G2 = *reinterpret_cast<const float2*>(grow0 + 2 * H_);
    float2 G3 = *reinterpret_cast<const float2*>(grow0 + 3 * H_);

    for (int t = 0; t < T_; t++) {
        const __half* hin  = (t & 1) ? g_hB : g_hA;
        __half*       hout = (t & 1) ? g_hA : g_hB;

        float acc[4][2][4];              // [m-frag][gate][c-regs]
#pragma unroll
        for (int mf = 0; mf < 4; mf++)
#pragma unroll
            for (int nt = 0; nt < 2; nt++)
#pragma unroll
                for (int r = 0; r < 4; r++) acc[mf][nt][r] = 0.0f;

        // 4-deep pipelined K loop over my 16 k16 bursts
        unsigned a[4][4][4];
        load_burst(a[0], hin, kq * 256,      grp, tq);
        load_burst(a[1], hin, kq * 256 + 16, grp, tq);
        load_burst(a[2], hin, kq * 256 + 32, grp, tq);
#pragma unroll
        for (int i = 0; i < 16; i++) {
            if (i < 13)
                load_burst(a[(i + 3) & 3], hin,
                           kq * 256 + (i + 3) * 16, grp, tq);
            unsigned (*ai)[4] = a[i & 3];
#pragma unroll
            for (int mf = 0; mf < 4; mf++)
#pragma unroll
                for (int nt = 0; nt < 2; nt++)
                    mma16(acc[mf][nt], ai[mf][0], ai[mf][1], ai[mf][2], ai[mf][3],
                          bw[i][nt][0], bw[i][nt][1]);
        }

        // stage my K-split partial (slab = kq; cols split by nh)
        {
            float* pr = preS + kq * PRE_FL;
#pragma unroll
            for (int mf = 0; mf < 4; mf++) {
                const int rm = mf * 16 + grp;
#pragma unroll
                for (int nt = 0; nt < 2; nt++) {
                    const int cn = (nh * 2 + nt) * 8 + 2 * tq;
                    *reinterpret_cast<float2*>(&pr[rm * PP + cn]) =
                        make_float2(acc[mf][nt][0], acc[mf][nt][1]);
                    *reinterpret_cast<float2*>(&pr[(rm + 8) * PP + cn]) =
                        make_float2(acc[mf][nt][2], acc[mf][nt][3]);
                }
            }
        }
        __syncthreads();

        // elementwise: 2 cells per thread, summing the 4 K-split partials
        {
            float i0 = G0.x, i1 = G0.y, f0 = G1.x, f1 = G1.y;
            float g0 = G2.x, g1 = G2.y, o0 = G3.x, o1 = G3.y;
#pragma unroll
            for (int p = 0; p < NPART; p++) {
                const float* pr = preS + p * PRE_FL + eb * PP;
                float2 v;
                v = *reinterpret_cast<const float2*>(&pr[ejj]);
                i0 += v.x; i1 += v.y;
                v = *reinterpret_cast<const float2*>(&pr[8 + ejj]);
                f0 += v.x; f1 += v.y;
                v = *reinterpret_cast<const float2*>(&pr[16 + ejj]);
                g0 += v.x; g1 += v.y;
                v = *reinterpret_cast<const float2*>(&pr[24 + ejj]);
                o0 += v.x; o1 += v.y;
            }
            i0 = fsig(i0); i1 = fsig(i1);
            f0 = fsig(f0); f1 = fsig(f1);
            o0 = fsig(o0); o1 = fsig(o1);
            g0 = ftanh(g0); g1 = ftanh(g1);
            creg.x = f0 * creg.x + i0 * g0;
            creg.y = f1 * creg.y + i1 * g1;
            float hx = o0 * ftanh(creg.x);
            float hy = o1 * ftanh(creg.y);
            unsigned hp = pack_h2(hx, hy);
            *reinterpret_cast<unsigned*>(&hout[eb * H_ + jg0]) = hp;
            *reinterpret_cast<unsigned*>(
                &seqout[(size_t)(t * B_ + eb) * H_ + jg0]) = hp;
        }

        // prefetch next step's gates BEFORE the barrier (independent of h)
        if (t + 1 < T_) {
            const float* grow = g_gates + ((size_t)((t + 1) * B_ + eb)) * G_ + jg0;
            G0 = *reinterpret_cast<const float2*>(grow);
            G1 = *reinterpret_cast<const float2*>(grow + H_);
            G2 = *reinterpret_cast<const float2*>(grow + 2 * H_);
            G3 = *reinterpret_cast<const float2*>(grow + 3 * H_);
        }

        flag_barrier(jb, tid, t + 1);
    }
}

// ---------------------------------------------------------------------------
// Final FC: reads fp16 final h (layer 3 seq = g_seqh1, t = 511), fp32 accum.
// ---------------------------------------------------------------------------
__global__ void __launch_bounds__(256)
fc_kernel(const float* __restrict__ fc_w, const float* __restrict__ fc_b,
          float* __restrict__ out)
{
    int b = blockIdx.x;
    int o = threadIdx.x;
    const __half2* hv = reinterpret_cast<const __half2*>(
        &g_seqh1[(size_t)((T_ - 1) * B_ + b) * H_]);
    const float2* wv = reinterpret_cast<const float2*>(&fc_w[(size_t)o * H_]);
    float s = 0.0f;
#pragma unroll 8
    for (int k = 0; k < H_ / 2; k++) {
        float2 a = __half22float2(hv[k]);
        float2 w = wv[k];
        s += a.x * w.x + a.y * w.y;
    }
    out[b * O_ + o] = s + fc_b[o];
}

// ---------------------------------------------------------------------------
// Launch: 11 graph nodes (conv_x + conv_w + 4 GEMM + 4 persist + FC)
// ---------------------------------------------------------------------------
extern "C" void kernel_launch(void* const* d_in, const int* in_sizes, int n_in,
                              void* d_out, int out_size)
{
    (void)in_sizes; (void)n_in; (void)out_size;
    const float* x    = (const float*)d_in[0];
    const float* Wih  = (const float*)d_in[1];
    const float* Whh  = (const float*)d_in[2];
    const float* bih  = (const float*)d_in[3];
    const float* bhh  = (const float*)d_in[4];
    const float* fc_w = (const float*)d_in[5];
    const float* fc_b = (const float*)d_in[6];
    float* out = (float*)d_out;

    cudaFuncSetAttribute(lstm_persist_tc,
                         cudaFuncAttributeMaxDynamicSharedMemorySize, PSMEM_BYTES);

    conv_x<<<TB_, 256>>>(x);
    conv_w<<<L_ * G_, 256>>>(Wih);

    const dim3 ggrid(G_ / BN, TB_ / BM);   // (32, 256)
    const int out_sel[L_] = { 0, 1, 0, 1 };

    for (int l = 0; l < L_; l++) {
        void* a_ptr = nullptr;
        if (l == 0) {
            cudaGetSymbolAddress(&a_ptr, g_xh);
        } else if (out_sel[l - 1] == 0) {
            cudaGetSymbolAddress(&a_ptr, g_seqh0);
        } else {
            cudaGetSymbolAddress(&a_ptr, g_seqh1);
        }
        gemm_gates_h<<<ggrid, 256>>>((const __half*)a_ptr, bih, bhh, l);
        lstm_persist_tc<<<NBLK, NTHR, PSMEM_BYTES>>>(Whh, l, out_sel[l]);
    }
    fc_kernel<<<B_, 256>>>(fc_w, fc_b, out);
}

// round 15
// speedup vs baseline: 1.6354x; 1.6354x over previous
#include <cuda_runtime.h>
#include <cuda_fp16.h>
#include <math.h>
#include <stddef.h>
#include <stdint.h>
#include <mma.h>

using namespace nvcuda;

// Problem dims (fixed)
#define B_   64
#define T_   512
#define D_   1024
#define H_   1024
#define L_   4
#define G_   4096           // 4*H
#define O_   256
#define TB_  (T_ * B_)      // 32768

#define NBLK 128            // persistent-kernel grid
#define NTHR 256

// ---------------------------------------------------------------------------
// Device scratch (static globals — no allocation allowed)
// ---------------------------------------------------------------------------
__device__ float  g_gates[(size_t)TB_ * G_];     // 512 MB
__device__ __half g_xh  [(size_t)TB_ * D_];      // 64 MB
__device__ __half g_wh  [(size_t)L_ * G_ * H_];  // 32 MB: ALL layers' Wih fp16
__device__ __half g_seqh0[(size_t)TB_ * H_];     // 64 MB
__device__ __half g_seqh1[(size_t)TB_ * H_];     // 64 MB
__device__ __half g_hA[B_ * H_];
__device__ __half g_hB[B_ * H_];

__device__ unsigned g_bar_count = 0;
__device__ unsigned g_bar_gen   = 0;
__device__ int      g_flags[NBLK * 32];          // one 128B line per block

// ---------------------------------------------------------------------------
// Atomic grid barrier (self-resetting; used ONCE per layer for init)
// ---------------------------------------------------------------------------
__device__ __forceinline__ void grid_barrier_atomic() {
    __threadfence();
    __syncthreads();
    if (threadIdx.x == 0) {
        unsigned gen = *(volatile unsigned*)&g_bar_gen;
        unsigned old = atomicAdd(&g_bar_count, 1u);
        if (old == NBLK - 1) {
            g_bar_count = 0;
            __threadfence();
            atomicAdd(&g_bar_gen, 1u);
        } else {
            while (*(volatile unsigned*)&g_bar_gen == gen) { }
        }
        __threadfence();
    }
    __syncthreads();
}

// ---------------------------------------------------------------------------
// Distributed flag barrier (per-step): no atomic serialization.
// ---------------------------------------------------------------------------
__device__ __forceinline__ void flag_barrier(int jb, int tid, int val) {
    __threadfence();
    __syncthreads();
    if (tid == 0)
        *((volatile int*)&g_flags[jb * 32]) = val;
    if (tid < NBLK) {
        volatile int* f = &g_flags[tid * 32];
        while (*f < val) { }
    }
    __syncthreads();
}

// ---------------------------------------------------------------------------
// cp.async helpers
// ---------------------------------------------------------------------------
__device__ __forceinline__ uint32_t smem_u32(const void* p) {
    uint32_t a;
    asm("{ .reg .u64 t; cvta.to.shared.u64 t, %1; cvt.u32.u64 %0, t; }"
        : "=r"(a) : "l"(p));
    return a;
}
__device__ __forceinline__ void cp16(uint32_t dst, const void* src) {
    asm volatile("cp.async.cg.shared.global [%0], [%1], 16;"
                 :: "r"(dst), "l"(src));
}
__device__ __forceinline__ void cp_commit() {
    asm volatile("cp.async.commit_group;" ::: "memory");
}
template <int N>
__device__ __forceinline__ void cp_wait() {
    asm volatile("cp.async.wait_group %0;" :: "n"(N) : "memory");
}

// fp16 mma: D(16x8,f32) += A(16x16,f16,row) * B(16x8,f16,col)
__device__ __forceinline__ void mma16(float* c,
                                      unsigned a0, unsigned a1,
                                      unsigned a2, unsigned a3,
                                      unsigned b0, unsigned b1) {
    asm volatile(
        "mma.sync.aligned.m16n8k16.row.col.f32.f16.f16.f32 "
        "{%0,%1,%2,%3}, {%4,%5,%6,%7}, {%8,%9}, {%0,%1,%2,%3};"
        : "+f"(c[0]), "+f"(c[1]), "+f"(c[2]), "+f"(c[3])
        : "r"(a0), "r"(a1), "r"(a2), "r"(a3), "r"(b0), "r"(b1));
}

__device__ __forceinline__ unsigned pack_h2(float x, float y) {
    __half2 h = __floats2half2_rn(x, y);
    return *reinterpret_cast<unsigned*>(&h);
}

// fast sigmoid / tanh (MUFU-based)
__device__ __forceinline__ float fsig(float x) {
    return __fdividef(1.0f, 1.0f + __expf(-x));
}
__device__ __forceinline__ float ftanh(float x) {
    return 1.0f - __fdividef(2.0f, __expf(2.0f * x) + 1.0f);
}

// ---------------------------------------------------------------------------
// One-time converts
// ---------------------------------------------------------------------------
__global__ void __launch_bounds__(256)
conv_x(const float* __restrict__ x)
{
    const int m = blockIdx.x;              // t*B + b
    const int t = m >> 6, b = m & 63;
    const float4* src = reinterpret_cast<const float4*>(
        x + ((size_t)b * T_ + t) * D_);
    __half2* dst = reinterpret_cast<__half2*>(g_xh + (size_t)m * D_);
    for (int i = threadIdx.x; i < D_ / 4; i += 256) {
        float4 v = src[i];
        dst[2 * i]     = __floats2half2_rn(v.x, v.y);
        dst[2 * i + 1] = __floats2half2_rn(v.z, v.w);
    }
}

// ALL layers' Wih fp32 -> g_wh fp16 (one launch)
__global__ void __launch_bounds__(256)
conv_w(const float* __restrict__ Wih_all)
{
    const int r = blockIdx.x;              // 0..(L*G-1)
    const float4* src = reinterpret_cast<const float4*>(
        Wih_all + (size_t)r * H_);
    __half2* dst = reinterpret_cast<__half2*>(g_wh + (size_t)r * H_);
    for (int i = threadIdx.x; i < H_ / 4; i += 256) {
        float4 v = src[i];
        dst[2 * i]     = __floats2half2_rn(v.x, v.y);
        dst[2 * i + 1] = __floats2half2_rn(v.z, v.w);
    }
}

// ===========================================================================
// fp16 input GEMM (proven):
//   gates[m, n] = bias[n] + sum_k A[m,k] * W[n,k]
// ===========================================================================
#define BM 128
#define BN 128
#define BKH 32
#define APH 40
#define STGH (BM * APH)
#define CPITCH 68
#define GEMM_SM_BYTES (4 * STGH * 2 + 512)

__device__ __forceinline__ void load_stage_h(__half* smh, int s, int c,
                                             const __half* __restrict__ A,
                                             const __half* __restrict__ W,
                                             int m0, int n0, int tid)
{
    const int k0 = c * BKH;
    __half* as = smh + s * STGH;
    __half* ws = smh + 2 * STGH + s * STGH;
#pragma unroll
    for (int i = 0; i < 2; i++) {
        int idx = tid + i * 256;
        int row = idx >> 2, seg = idx & 3;
        cp16(smem_u32(&as[row * APH + seg * 8]),
             A + (size_t)(m0 + row) * H_ + k0 + seg * 8);
    }
#pragma unroll
    for (int i = 0; i < 2; i++) {
        int idx = tid + i * 256;
        int row = idx >> 2, seg = idx & 3;
        cp16(smem_u32(&ws[row * APH + seg * 8]),
             W + (size_t)(n0 + row) * H_ + k0 + seg * 8);
    }
    cp_commit();
}

__global__ void __launch_bounds__(256)
gemm_gates_h(const __half* __restrict__ A,
             const float* __restrict__ bih_all,
             const float* __restrict__ bhh_all,
             int layer)
{
    __shared__ __align__(16) char smraw[GEMM_SM_BYTES];
    __half* smh   = reinterpret_cast<__half*>(smraw);
    float*  biasS = reinterpret_cast<float*>(smraw + 4 * STGH * 2);
    float*  Cbuf  = reinterpret_cast<float*>(smraw);

    const __half* W = g_wh + (size_t)layer * G_ * H_;

    const int tid = threadIdx.x;
    const int n0  = blockIdx.x * BN;
    const int m0  = blockIdx.y * BM;
    const int wid = tid >> 5;
    const int wm  = wid & 3;
    const int wn  = wid >> 2;

    if (tid < 128)
        biasS[tid] = bih_all[(size_t)layer * G_ + n0 + tid]
                   + bhh_all[(size_t)layer * G_ + n0 + tid];

    wmma::fragment<wmma::accumulator, 16, 16, 16, float> cf[2][4];
#pragma unroll
    for (int i = 0; i < 2; i++)
#pragma unroll
        for (int j = 0; j < 4; j++) wmma::fill_fragment(cf[i][j], 0.0f);

    load_stage_h(smh, 0, 0, A, W, m0, n0, tid);

    const int NC = H_ / BKH;
    for (int c = 0; c < NC; c++) {
        const int s = c & 1;
        if (c + 1 < NC) {
            load_stage_h(smh, s ^ 1, c + 1, A, W, m0, n0, tid);
            cp_wait<1>();
        } else {
            cp_wait<0>();
        }
        __syncthreads();

        const __half* as = smh + s * STGH;
        const __half* ws = smh + 2 * STGH + s * STGH;
#pragma unroll
        for (int kk = 0; kk < BKH; kk += 16) {
            wmma::fragment<wmma::matrix_a, 16, 16, 16, __half,
                           wmma::row_major> af[2];
            wmma::fragment<wmma::matrix_b, 16, 16, 16, __half,
                           wmma::col_major> bf[4];
#pragma unroll
            for (int i = 0; i < 2; i++)
                wmma::load_matrix_sync(af[i],
                    as + (wm * 32 + i * 16) * APH + kk, APH);
#pragma unroll
            for (int j = 0; j < 4; j++)
                wmma::load_matrix_sync(bf[j],
                    ws + (wn * 64 + j * 16) * APH + kk, APH);
#pragma unroll
            for (int i = 0; i < 2; i++)
#pragma unroll
                for (int j = 0; j < 4; j++)
                    wmma::mma_sync(cf[i][j], af[i], bf[j], cf[i][j]);
        }
        __syncthreads();
    }

#pragma unroll
    for (int half = 0; half < 2; half++) {
        if (wn == half) {
#pragma unroll
            for (int i = 0; i < 2; i++)
#pragma unroll
                for (int j = 0; j < 4; j++)
                    wmma::store_matrix_sync(
                        &Cbuf[(wm * 32 + i * 16) * CPITCH + j * 16],
                        cf[i][j], CPITCH, wmma::mem_row_major);
        }
        __syncthreads();
#pragma unroll
        for (int q = 0; q < 8; q++) {
            int lin = q * 256 + tid;
            int row = lin >> 4;
            int c4  = lin & 15;
            float4 v = *reinterpret_cast<const float4*>(&Cbuf[row * CPITCH + c4 * 4]);
            int n = half * 64 + c4 * 4;
            v.x += biasS[n + 0];
            v.y += biasS[n + 1];
            v.z += biasS[n + 2];
            v.w += biasS[n + 3];
            *reinterpret_cast<float4*>(
                &g_gates[(size_t)(m0 + row) * G_ + n0 + n]) = v;
        }
        __syncthreads();
    }
}

// ===========================================================================
// Persistent recurrent kernel (R13 design restored — best measured):
// 8 warps = 8 K-eighths; Whh fp16 fragments in registers; h fp16 ping-pong;
// 2-deep pipelined 16-load bursts + mma16; flag barrier; fast MUFU gates.
// R15 addition: next step's gate loads issued BEFORE the flag barrier.
// ===========================================================================
#define PP 36
#define PRE_FL (64 * PP)
#define NPART 8
#define PSMEM_BYTES (NPART * PRE_FL * 4)       // 73,728 B

__device__ __forceinline__ void load_burst(unsigned a[4][4],
                                           const __half* __restrict__ hin,
                                           int kb, int grp, int tq)
{
#pragma unroll
    for (int mf = 0; mf < 4; mf++) {
        const unsigned* p0 = reinterpret_cast<const unsigned*>(
            hin + (mf * 16 + grp) * H_ + kb) + tq;
        const unsigned* p1 = p0 + 4 * H_;      // +8 rows
        a[mf][0] = __ldcg(p0);
        a[mf][1] = __ldcg(p1);
        a[mf][2] = __ldcg(p0 + 4);
        a[mf][3] = __ldcg(p1 + 4);
    }
}

__global__ void __launch_bounds__(NTHR, 1)
lstm_persist_tc(const float* __restrict__ Whh_all, int layer, int out_sel)
{
    extern __shared__ float preS[];            // [8][64][PP]

    const float* W      = Whh_all + (size_t)layer * G_ * H_;
    __half*      seqout = (out_sel == 0) ? g_seqh0 : g_seqh1;

    const int jb   = blockIdx.x;
    const int tid  = threadIdx.x;
    const int lane = tid & 31;
    const int wid  = tid >> 5;       // K-eighth
    const int grp  = lane >> 2;      // 0..7
    const int tq   = lane & 3;       // 0..3

    const int eb  = tid >> 2;
    const int ejj = (tid & 3) * 2;
    const int jg0 = jb * 8 + ejj;

    // Whh B-fragments -> registers (fp16)
    unsigned bw[8][4][2];
    {
        const float* wbase = W + (size_t)(jb * 8 + grp) * H_ + wid * 128 + 2 * tq;
#pragma unroll
        for (int nt = 0; nt < 4; nt++) {
            const float* wr = wbase + (size_t)nt * H_ * H_;
#pragma unroll
            for (int k16 = 0; k16 < 8; k16++) {
                bw[k16][nt][0] = pack_h2(wr[k16 * 16],     wr[k16 * 16 + 1]);
                bw[k16][nt][1] = pack_h2(wr[k16 * 16 + 8], wr[k16 * 16 + 9]);
            }
        }
    }

    // zero initial h + reset my flag (behind the atomic barrier)
    reinterpret_cast<unsigned*>(g_hA)[jb * 256 + tid] = 0u;
    reinterpret_cast<unsigned*>(g_hB)[jb * 256 + tid] = 0u;
    if (tid == 0) g_flags[jb * 32] = 0;

    float2 creg = make_float2(0.0f, 0.0f);

    grid_barrier_atomic();

    // gates prefetch for t = 0
    const float* grow0 = g_gates + ((size_t)eb) * G_ + jg0;
    float2 G0 = *reinterpret_cast<const float2*>(grow0);
    float2 G1 = *reinterpret_cast<const float2*>(grow0 + H_);
    float2 G2 = *reinterpret_cast<const float2*>(grow0 + 2 * H_);
    float2 G3 = *reinterpret_cast<const float2*>(grow0 + 3 * H_);

    for (int t = 0; t < T_; t++) {
        const __half* hin  = (t & 1) ? g_hB : g_hA;
        __half*       hout = (t & 1) ? g_hA : g_hB;

        float acc[4][4][4];
#pragma unroll
        for (int mf = 0; mf < 4; mf++)
#pragma unroll
            for (int nt = 0; nt < 4; nt++)
#pragma unroll
                for (int r = 0; r < 4; r++) acc[mf][nt][r] = 0.0f;

        // 2-deep pipelined K loop over my 8 k16 bursts
        unsigned a[2][4][4];
        load_burst(a[0], hin, wid * 128, grp, tq);
#pragma unroll
        for (int i = 0; i < 8; i++) {
            if (i < 7)
                load_burst(a[(i + 1) & 1], hin, wid * 128 + (i + 1) * 16, grp, tq);
            unsigned (*ai)[4] = a[i & 1];
#pragma unroll
            for (int mf = 0; mf < 4; mf++)
#pragma unroll
                for (int nt = 0; nt < 4; nt++)
                    mma16(acc[mf][nt], ai[mf][0], ai[mf][1], ai[mf][2], ai[mf][3],
                          bw[i][nt][0], bw[i][nt][1]);
        }

        // stage my K-split partial
        {
            float* pr = preS + wid * PRE_FL;
#pragma unroll
            for (int mf = 0; mf < 4; mf++) {
                const int rm = mf * 16 + grp;
#pragma unroll
                for (int nt = 0; nt < 4; nt++) {
                    const int cn = nt * 8 + 2 * tq;
                    *reinterpret_cast<float2*>(&pr[rm * PP + cn]) =
                        make_float2(acc[mf][nt][0], acc[mf][nt][1]);
                    *reinterpret_cast<float2*>(&pr[(rm + 8) * PP + cn]) =
                        make_float2(acc[mf][nt][2], acc[mf][nt][3]);
                }
            }
        }
        __syncthreads();

        // elementwise: 2 cells per thread, summing the 8 K-split partials
        {
            float i0 = G0.x, i1 = G0.y, f0 = G1.x, f1 = G1.y;
            float g0 = G2.x, g1 = G2.y, o0 = G3.x, o1 = G3.y;
#pragma unroll
            for (int p = 0; p < NPART; p++) {
                const float* pr = preS + p * PRE_FL + eb * PP;
                float2 v;
                v = *reinterpret_cast<const float2*>(&pr[ejj]);
                i0 += v.x; i1 += v.y;
                v = *reinterpret_cast<const float2*>(&pr[8 + ejj]);
                f0 += v.x; f1 += v.y;
                v = *reinterpret_cast<const float2*>(&pr[16 + ejj]);
                g0 += v.x; g1 += v.y;
                v = *reinterpret_cast<const float2*>(&pr[24 + ejj]);
                o0 += v.x; o1 += v.y;
            }
            i0 = fsig(i0); i1 = fsig(i1);
            f0 = fsig(f0); f1 = fsig(f1);
            o0 = fsig(o0); o1 = fsig(o1);
            g0 = ftanh(g0); g1 = ftanh(g1);
            creg.x = f0 * creg.x + i0 * g0;
            creg.y = f1 * creg.y + i1 * g1;
            float hx = o0 * ftanh(creg.x);
            float hy = o1 * ftanh(creg.y);
            unsigned hp = pack_h2(hx, hy);
            *reinterpret_cast<unsigned*>(&hout[eb * H_ + jg0]) = hp;
            *reinterpret_cast<unsigned*>(
                &seqout[(size_t)(t * B_ + eb) * H_ + jg0]) = hp;
        }

        // prefetch next step's gates BEFORE the barrier (independent of h)
        if (t + 1 < T_) {
            const float* grow = g_gates + ((size_t)((t + 1) * B_ + eb)) * G_ + jg0;
            G0 = *reinterpret_cast<const float2*>(grow);
            G1 = *reinterpret_cast<const float2*>(grow + H_);
            G2 = *reinterpret_cast<const float2*>(grow + 2 * H_);
            G3 = *reinterpret_cast<const float2*>(grow + 3 * H_);
        }

        flag_barrier(jb, tid, t + 1);
    }
}

// ---------------------------------------------------------------------------
// Final FC: reads fp16 final h (layer 3 seq = g_seqh1, t = 511), fp32 accum.
// ---------------------------------------------------------------------------
__global__ void __launch_bounds__(256)
fc_kernel(const float* __restrict__ fc_w, const float* __restrict__ fc_b,
          float* __restrict__ out)
{
    int b = blockIdx.x;
    int o = threadIdx.x;
    const __half2* hv = reinterpret_cast<const __half2*>(
        &g_seqh1[(size_t)((T_ - 1) * B_ + b) * H_]);
    const float2* wv = reinterpret_cast<const float2*>(&fc_w[(size_t)o * H_]);
    float s = 0.0f;
#pragma unroll 8
    for (int k = 0; k < H_ / 2; k++) {
        float2 a = __half22float2(hv[k]);
        float2 w = wv[k];
        s += a.x * w.x + a.y * w.y;
    }
    out[b * O_ + o] = s + fc_b[o];
}

// ---------------------------------------------------------------------------
// Launch: 11 graph nodes (conv_x + conv_w + 4 GEMM + 4 persist + FC)
// ---------------------------------------------------------------------------
extern "C" void kernel_launch(void* const* d_in, const int* in_sizes, int n_in,
                              void* d_out, int out_size)
{
    (void)in_sizes; (void)n_in; (void)out_size;
    const float* x    = (const float*)d_in[0];
    const float* Wih  = (const float*)d_in[1];
    const float* Whh  = (const float*)d_in[2];
    const float* bih  = (const float*)d_in[3];
    const float* bhh  = (const float*)d_in[4];
    const float* fc_w = (const float*)d_in[5];
    const float* fc_b = (const float*)d_in[6];
    float* out = (float*)d_out;

    cudaFuncSetAttribute(lstm_persist_tc,
                         cudaFuncAttributeMaxDynamicSharedMemorySize, PSMEM_BYTES);

    conv_x<<<TB_, 256>>>(x);
    conv_w<<<L_ * G_, 256>>>(Wih);

    const dim3 ggrid(G_ / BN, TB_ / BM);   // (32, 256)
    const int out_sel[L_] = { 0, 1, 0, 1 };

    for (int l = 0; l < L_; l++) {
        void* a_ptr = nullptr;
        if (l == 0) {
            cudaGetSymbolAddress(&a_ptr, g_xh);
        } else if (out_sel[l - 1] == 0) {
            cudaGetSymbolAddress(&a_ptr, g_seqh0);
        } else {
            cudaGetSymbolAddress(&a_ptr, g_seqh1);
        }
        gemm_gates_h<<<ggrid, 256>>>((const __half*)a_ptr, bih, bhh, l);
        lstm_persist_tc<<<NBLK, NTHR, PSMEM_BYTES>>>(Whh, l, out_sel[l]);
    }
    fc_kernel<<<B_, 256>>>(fc_w, fc_b, out);
}